// round 1
// baseline (speedup 1.0000x reference)
#include <cuda_runtime.h>
#include <cstdint>

// Shapes (fixed by the problem)
#define BB 4
#define CC 256
#define HH 56
#define WW 56
#define CO 128
#define NT 49   // 7x7 taps

typedef unsigned long long u64;

// Scratch (device globals: no allocations allowed)
__device__ float g_k1[BB * CO * HH * WW];    // conv1 output (+bias)
__device__ float g_attn[BB * NT * HH * WW];  // softmax attention

// ---------- packed fp32x2 helpers (SASS FFMA2) ----------
__device__ __forceinline__ u64 pack2(float x, float y) {
    u64 r;
    asm("mov.b64 %0, {%1, %2};" : "=l"(r)
        : "r"(__float_as_uint(x)), "r"(__float_as_uint(y)));
    return r;
}
__device__ __forceinline__ void fma2(u64& d, u64 a, u64 b) {
    asm("fma.rn.f32x2 %0, %1, %2, %0;" : "+l"(d) : "l"(a), "l"(b));
}
__device__ __forceinline__ float2 unpack2(u64 v) {
    float2 f;
    asm("mov.b64 {%0, %1}, %2;" : "=f"(f.x), "=f"(f.y) : "l"(v));
    return f;
}
__device__ __forceinline__ u64 lds64(const float* p) {
    return *reinterpret_cast<const u64*>(p);
}

// =====================================================================
// Kernel A: conv1 (7x7, dilation 2, pad 6) + bias  -> g_k1
// Grid (56, 4, 2): h, b, co-half(64).  224 threads.
// Block tile: 64 co x 56 px (one output row).
// Thread tile: 4 co x 4 px (2 pixel-pairs) -> 8 packed f32x2 accumulators.
// K loop: ci in chunks of 2, all 49 taps per ci.
// =====================================================================
__global__ void __launch_bounds__(224) conv1_kernel(
    const float* __restrict__ x, const float* __restrict__ W1,
    const float* __restrict__ b1)
{
    __shared__ __align__(16) float xs[2][7][68];   // 2 ci x 7 rows x cols [-6..61]
    __shared__ __align__(16) float ws[98 * 68];    // ws[k][co], k=(cil,tap), pad 68

    const int h = blockIdx.x;
    const int b = blockIdx.y;
    const int co_base = blockIdx.z * 64;
    const int tid = threadIdx.x;
    const int cg = tid & 15;          // 16 co-quads
    const int pg = tid >> 4;          // 14 pixel groups
    const int p0 = pg * 4;            // 4 px per thread (even -> 8B aligned pairs)
    const int co0 = co_base + 4 * cg;

    u64 acc[8];
#pragma unroll
    for (int t = 0; t < 8; ++t) acc[t] = 0ull;  // bits 0 == (+0.f, +0.f)

    for (int cc = 0; cc < CC; cc += 2) {
        __syncthreads();
        // ---- load x tile (2 ci, 7 dilated rows, 68 cols, zero-padded) ----
        for (int t = tid; t < 2 * 7 * 68; t += 224) {
            int cil = t / 476, r = t - cil * 476;
            int i = r / 68, col = r - i * 68;
            int row = h - 6 + 2 * i;
            int gcol = col - 6;
            float v = 0.f;
            if (row >= 0 && row < HH && gcol >= 0 && gcol < WW)
                v = x[((b * CC + cc + cil) * HH + row) * WW + gcol];
            xs[cil][i][col] = v;
        }
        // ---- load weights, transposed to ws[k][co] (reads coalesced over tap) ----
        for (int t = tid; t < 64 * 98; t += 224) {
            int co = t / 98, r = t - co * 98;
            int cil = r / 49, tap = r - cil * 49;
            ws[(cil * 49 + tap) * 68 + co] =
                W1[((co_base + co) * CC + cc + cil) * 49 + tap];
        }
        __syncthreads();

#pragma unroll 1
        for (int cil = 0; cil < 2; ++cil) {
#pragma unroll
            for (int i = 0; i < 7; ++i) {
                const float* xrow = &xs[cil][i][p0];
                const float* wrow = &ws[(cil * 49 + i * 7) * 68 + 4 * cg];
                u64 xa = lds64(xrow);        // px (p0+2j, p0+2j+1)
                u64 xb = lds64(xrow + 2);    // px (p0+2j+2, p0+2j+3)
#pragma unroll
                for (int j = 0; j < 7; ++j) {
                    float4 wv = *reinterpret_cast<const float4*>(wrow + j * 68);
                    u64 w0 = pack2(wv.x, wv.x);
                    u64 w1 = pack2(wv.y, wv.y);
                    u64 w2 = pack2(wv.z, wv.z);
                    u64 w3 = pack2(wv.w, wv.w);
                    fma2(acc[0], w0, xa); fma2(acc[1], w0, xb);
                    fma2(acc[2], w1, xa); fma2(acc[3], w1, xb);
                    fma2(acc[4], w2, xa); fma2(acc[5], w2, xb);
                    fma2(acc[6], w3, xa); fma2(acc[7], w3, xb);
                    xa = xb;
                    if (j < 6) xb = lds64(xrow + 2 * j + 4);
                }
            }
        }
    }

    // ---- epilogue: + bias, store pairs ----
#pragma unroll
    for (int c = 0; c < 4; ++c) {
        float bias = b1[co0 + c];
#pragma unroll
        for (int pr = 0; pr < 2; ++pr) {
            float2 v = unpack2(acc[c * 2 + pr]);
            int idx = ((b * CO + co0 + c) * HH + h) * WW + p0 + 2 * pr;
            *reinterpret_cast<float2*>(&g_k1[idx]) =
                make_float2(v.x + bias, v.y + bias);
        }
    }
}

// =====================================================================
// Kernel B: conv2 (1x1, 128->49) + bias + softmax over 49 -> g_attn
// Grid (56, 4), 256 threads. Tiny kernel.
// =====================================================================
__global__ void __launch_bounds__(256) conv2_softmax_kernel(
    const float* __restrict__ W2, const float* __restrict__ b2)
{
    __shared__ float k1s[128][57];
    __shared__ float ls[49][57];
    const int h = blockIdx.x;
    const int b = blockIdx.y;
    const int tid = threadIdx.x;

    for (int t = tid; t < 128 * 56; t += 256) {
        int c = t / 56, p = t - c * 56;
        k1s[c][p] = g_k1[((b * CO + c) * HH + h) * WW + p];
    }
    __syncthreads();

    for (int idx = tid; idx < 49 * 56; idx += 256) {
        int kk = idx / 56, p = idx - kk * 56;
        float acc = b2[kk];
        const float* wr = &W2[kk * 128];
#pragma unroll 8
        for (int c = 0; c < 128; ++c)
            acc += __ldg(&wr[c]) * k1s[c][p];
        ls[kk][p] = acc;
    }
    __syncthreads();

    if (tid < 56) {
        int p = tid;
        float m = -1e30f;
#pragma unroll
        for (int kk = 0; kk < 49; ++kk) m = fmaxf(m, ls[kk][p]);
        float s = 0.f;
#pragma unroll
        for (int kk = 0; kk < 49; ++kk) {
            float e = expf(ls[kk][p] - m);
            ls[kk][p] = e;
            s += e;
        }
        float inv = 1.f / s;
#pragma unroll
        for (int kk = 0; kk < 49; ++kk) ls[kk][p] *= inv;
    }
    __syncthreads();

    for (int t = tid; t < 49 * 56; t += 256) {
        int kk = t / 56, p = t - kk * 56;
        g_attn[((b * NT + kk) * HH + h) * WW + p] = ls[kk][p];
    }
}

// =====================================================================
// Kernel C: weighted local sum over 49 dilated taps -> out
// Grid (56, 4, 2): h, b, c-half(128).  224 threads.
// Per ci-chunk of 16: thread computes 1 channel x 4 px (2 f32x2 pairs).
// =====================================================================
__global__ void __launch_bounds__(224) gather_kernel(
    const float* __restrict__ x, float* __restrict__ out)
{
    __shared__ __align__(16) float at[49][58];
    __shared__ __align__(16) float xs[16][7][68];
    const int h = blockIdx.x;
    const int b = blockIdx.y;
    const int chalf = blockIdx.z * 128;
    const int tid = threadIdx.x;

    for (int t = tid; t < 49 * 56; t += 224) {
        int kk = t / 56, p = t - kk * 56;
        at[kk][p] = g_attn[((b * NT + kk) * HH + h) * WW + p];
    }

    const int pg = tid % 14;     // pixel group (coalesced-ish stores)
    const int cl = tid / 14;     // local channel 0..15
    const int p0 = pg * 4;

    for (int ch = 0; ch < 8; ++ch) {
        __syncthreads();
        for (int t = tid; t < 16 * 476; t += 224) {
            int c = t / 476, r = t - c * 476;
            int i = r / 68, col = r - i * 68;
            int row = h - 6 + 2 * i;
            int gcol = col - 6;
            float v = 0.f;
            if (row >= 0 && row < HH && gcol >= 0 && gcol < WW)
                v = x[((b * CC + chalf + ch * 16 + c) * HH + row) * WW + gcol];
            xs[c][i][col] = v;
        }
        __syncthreads();

        u64 a0 = 0ull, a1 = 0ull;
#pragma unroll
        for (int i = 0; i < 7; ++i) {
            const float* xrow = &xs[cl][i][p0];
#pragma unroll
            for (int j = 0; j < 7; ++j) {
                u64 av0 = lds64(&at[i * 7 + j][p0]);
                u64 av1 = lds64(&at[i * 7 + j][p0 + 2]);
                u64 xv0 = lds64(xrow + 2 * j);
                u64 xv1 = lds64(xrow + 2 * j + 2);
                fma2(a0, av0, xv0);
                fma2(a1, av1, xv1);
            }
        }
        int c = chalf + ch * 16 + cl;
        int o = ((b * CC + c) * HH + h) * WW + p0;
        float2 r0 = unpack2(a0), r1 = unpack2(a1);
        *reinterpret_cast<float2*>(&out[o]) = r0;
        *reinterpret_cast<float2*>(&out[o + 2]) = r1;
    }
}

// =====================================================================
extern "C" void kernel_launch(void* const* d_in, const int* in_sizes, int n_in,
                              void* d_out, int out_size)
{
    // Positional defaults (metadata order: x, W1, b1, W2, b2)
    const float* x  = (const float*)d_in[0];
    const float* W1 = (const float*)d_in[1];
    const float* b1 = (const float*)d_in[2];
    const float* W2 = (const float*)d_in[3];
    const float* b2 = (const float*)d_in[4];
    // Defensive: match by element count (all sizes are distinct)
    for (int i = 0; i < n_in; ++i) {
        switch (in_sizes[i]) {
            case BB * CC * HH * WW: x  = (const float*)d_in[i]; break;  // 3211264
            case CO * CC * NT:      W1 = (const float*)d_in[i]; break;  // 1605632
            case CO:                b1 = (const float*)d_in[i]; break;  // 128
            case NT * CO:           W2 = (const float*)d_in[i]; break;  // 6272
            case NT:                b2 = (const float*)d_in[i]; break;  // 49
            default: break;
        }
    }
    float* out = (float*)d_out;

    conv1_kernel<<<dim3(56, 4, 2), 224>>>(x, W1, b1);
    conv2_softmax_kernel<<<dim3(56, 4), 256>>>(W2, b2);
    gather_kernel<<<dim3(56, 4, 2), 224>>>(x, out);
}

// round 2
// speedup vs baseline: 1.0635x; 1.0635x over previous
#include <cuda_runtime.h>
#include <cstdint>

#define BB 4
#define CC 256
#define HH 56
#define WW 56
#define CO 128
#define NT 49
#define HW 3136

typedef unsigned long long u64;

// ---- device-global scratch (no allocations allowed) ----
__device__ __align__(16) u64   g_W1d[2 * CC * NT * 64];       // dup-packed weights, 12.8MB
__device__ __align__(16) float g_part[4 * BB * CO * HW];      // split-K partials, 25.7MB
__device__ __align__(16) float g_attn[BB * NT * HW];          // softmax attention

// ---------- packed fp32x2 helpers (SASS FFMA2) ----------
__device__ __forceinline__ u64 pack2(float x, float y) {
    u64 r;
    asm("mov.b64 %0, {%1, %2};" : "=l"(r)
        : "r"(__float_as_uint(x)), "r"(__float_as_uint(y)));
    return r;
}
__device__ __forceinline__ void fma2(u64& d, u64 a, u64 b) {
    asm("fma.rn.f32x2 %0, %1, %2, %0;" : "+l"(d) : "l"(a), "l"(b));
}
__device__ __forceinline__ float2 unpack2(u64 v) {
    float2 f;
    asm("mov.b64 {%0, %1}, %2;" : "=f"(f.x), "=f"(f.y) : "l"(v));
    return f;
}
__device__ __forceinline__ u64 lds64(const float* p) {
    return *reinterpret_cast<const u64*>(p);
}

// =====================================================================
// Kernel 0: duplicate-pack W1 into g_W1d[cb][ci][tap][co]  (u64 = (w,w))
// =====================================================================
__global__ void __launch_bounds__(256) prep_w1(const float* __restrict__ W1)
{
    int idx = blockIdx.x * 256 + threadIdx.x;   // 2*256*49*64 = 1,605,632
    int co  = idx & 63;
    int t   = idx >> 6;
    int tap = t % NT;
    int r   = t / NT;          // cb*256 + ci
    int ci  = r & 255;
    int cb  = r >> 8;
    float w = W1[((cb * 64 + co) * CC + ci) * NT + tap];
    g_W1d[idx] = pack2(w, w);
}

// =====================================================================
// Kernel A: conv1 (7x7 dil-2 pad-6) split-K partials -> g_part
// Grid (28, 4, 8): h-pair, b, (co-half * 4 ci-quarters). 224 threads.
// Thread: 1 h-row (hl) x 4 co x 8 px. 16 packed f32x2 accumulators.
// =====================================================================
__global__ void __launch_bounds__(224) conv1_kernel(const float* __restrict__ x)
{
    __shared__ __align__(16) u64   ws[NT * 64];     // [tap][co] dup-packed, 25088B
    __shared__ __align__(16) float xs[2][7][68];    // 2 rows x 7 dil-rows x cols[-6..61]

    const int b   = blockIdx.y;
    const int cb  = blockIdx.z >> 2;     // co half
    const int q   = blockIdx.z & 3;      // ci quarter
    const int ci0 = q * 64;
    const int tid = threadIdx.x;
    const int hl  = tid / 112;           // 0/1 within h-pair (warp-uniform)
    const int r   = tid - hl * 112;
    const int cg  = r & 15;              // 16 co-quads
    const int pg  = r >> 4;              // 7 pixel groups
    const int p0  = pg * 8;              // 8 px per thread
    const int h   = blockIdx.x * 2 + hl;

    u64 acc[16];
#pragma unroll
    for (int t = 0; t < 16; ++t) acc[t] = 0ull;   // bits 0 == (+0.f,+0.f)

    for (int ci = ci0; ci < ci0 + 64; ++ci) {
        __syncthreads();
        // ---- weights: straight coalesced copy (already packed + laid out) ----
        {
            const ulonglong2* src = reinterpret_cast<const ulonglong2*>(
                g_W1d + (size_t)(cb * CC + ci) * (NT * 64));
            ulonglong2* dst = reinterpret_cast<ulonglong2*>(ws);
#pragma unroll
            for (int t = 0; t < 7; ++t)           // 7*224 = 1568 x 16B
                dst[tid + t * 224] = src[tid + t * 224];
        }
        // ---- x tile: 2 rows x 7 dilated rows x 68 cols, zero-padded ----
        {
            const float* xp = x + ((size_t)b * CC + ci) * HW;
            const int h0 = blockIdx.x * 2;
#pragma unroll
            for (int t = 0; t < 5; ++t) {
                int e = tid + t * 224;
                if (e < 952) {
                    int hh  = e / 476; int rr = e - hh * 476;
                    int i   = rr / 68; int col = rr - i * 68;
                    int row = h0 + hh - 6 + 2 * i;
                    int gcol = col - 6;
                    float v = 0.f;
                    if ((unsigned)row < HH && (unsigned)gcol < WW)
                        v = xp[row * WW + gcol];
                    xs[hh][i][col] = v;
                }
            }
        }
        __syncthreads();

#pragma unroll
        for (int i = 0; i < 7; ++i) {
            const u64* xrow = reinterpret_cast<const u64*>(&xs[hl][i][p0]);
            const u64* wrow = &ws[i * 7 * 64 + 4 * cg];
            u64 xw0 = xrow[0], xw1 = xrow[1], xw2 = xrow[2], xw3 = xrow[3];
#pragma unroll
            for (int j = 0; j < 7; ++j) {
                ulonglong2 wa = *reinterpret_cast<const ulonglong2*>(wrow + j * 64);
                ulonglong2 wb = *reinterpret_cast<const ulonglong2*>(wrow + j * 64 + 2);
                fma2(acc[0],  wa.x, xw0); fma2(acc[1],  wa.x, xw1);
                fma2(acc[2],  wa.x, xw2); fma2(acc[3],  wa.x, xw3);
                fma2(acc[4],  wa.y, xw0); fma2(acc[5],  wa.y, xw1);
                fma2(acc[6],  wa.y, xw2); fma2(acc[7],  wa.y, xw3);
                fma2(acc[8],  wb.x, xw0); fma2(acc[9],  wb.x, xw1);
                fma2(acc[10], wb.x, xw2); fma2(acc[11], wb.x, xw3);
                fma2(acc[12], wb.y, xw0); fma2(acc[13], wb.y, xw1);
                fma2(acc[14], wb.y, xw2); fma2(acc[15], wb.y, xw3);
                xw0 = xw1; xw1 = xw2; xw2 = xw3;
                if (j < 6) xw3 = xrow[j + 4];
            }
        }
    }

    // ---- store partials (no bias here; added in kernel B) ----
#pragma unroll
    for (int c = 0; c < 4; ++c) {
        int co = cb * 64 + 4 * cg + c;
        float* dst = g_part + ((size_t)(q * BB + b) * CO + co) * HW + h * WW + p0;
#pragma unroll
        for (int m = 0; m < 4; ++m)
            reinterpret_cast<u64*>(dst)[m] = acc[c * 4 + m];
    }
}

// =====================================================================
// Kernel B: sum 4 split-K slices + b1, conv2 (1x1, 128->49) + b2,
//           softmax over 49 -> g_attn.  Grid (56,4), 256 threads.
// =====================================================================
__global__ void __launch_bounds__(256) conv2_softmax_kernel(
    const float* __restrict__ W2, const float* __restrict__ b1,
    const float* __restrict__ b2)
{
    __shared__ float k1s[128][57];
    __shared__ float ls[49][57];
    const int h = blockIdx.x;
    const int b = blockIdx.y;
    const int tid = threadIdx.x;

    for (int t = tid; t < 128 * 56; t += 256) {
        int c = t / 56, p = t - c * 56;
        size_t base = (size_t)(b * CO + c) * HW + h * WW + p;
        float v = b1[c];
#pragma unroll
        for (int q = 0; q < 4; ++q)
            v += g_part[(size_t)q * BB * CO * HW + base];
        k1s[c][p] = v;
    }
    __syncthreads();

    for (int idx = tid; idx < 49 * 56; idx += 256) {
        int kk = idx / 56, p = idx - kk * 56;
        float acc = b2[kk];
        const float* wr = &W2[kk * 128];
#pragma unroll 8
        for (int c = 0; c < 128; ++c)
            acc += __ldg(&wr[c]) * k1s[c][p];
        ls[kk][p] = acc;
    }
    __syncthreads();

    if (tid < 56) {
        int p = tid;
        float m = -1e30f;
#pragma unroll
        for (int kk = 0; kk < 49; ++kk) m = fmaxf(m, ls[kk][p]);
        float s = 0.f;
#pragma unroll
        for (int kk = 0; kk < 49; ++kk) {
            float e = expf(ls[kk][p] - m);
            ls[kk][p] = e;
            s += e;
        }
        float inv = 1.f / s;
#pragma unroll
        for (int kk = 0; kk < 49; ++kk) ls[kk][p] *= inv;
    }
    __syncthreads();

    for (int t = tid; t < 49 * 56; t += 256) {
        int kk = t / 56, p = t - kk * 56;
        g_attn[((size_t)b * NT + kk) * HW + h * WW + p] = ls[kk][p];
    }
}

// =====================================================================
// Kernel C: weighted local sum over 49 dilated taps -> out
// Grid (56, 4, 2), 224 threads.
// =====================================================================
__global__ void __launch_bounds__(224) gather_kernel(
    const float* __restrict__ x, float* __restrict__ out)
{
    __shared__ __align__(16) float at[49][58];
    __shared__ __align__(16) float xs[16][7][68];
    const int h = blockIdx.x;
    const int b = blockIdx.y;
    const int chalf = blockIdx.z * 128;
    const int tid = threadIdx.x;

    for (int t = tid; t < 49 * 56; t += 224) {
        int kk = t / 56, p = t - kk * 56;
        at[kk][p] = g_attn[((size_t)b * NT + kk) * HW + h * WW + p];
    }

    const int pg = tid % 14;
    const int cl = tid / 14;
    const int p0 = pg * 4;

    for (int ch = 0; ch < 8; ++ch) {
        __syncthreads();
        for (int t = tid; t < 16 * 476; t += 224) {
            int c = t / 476, rr = t - c * 476;
            int i = rr / 68, col = rr - i * 68;
            int row = h - 6 + 2 * i;
            int gcol = col - 6;
            float v = 0.f;
            if ((unsigned)row < HH && (unsigned)gcol < WW)
                v = x[((size_t)(b * CC + chalf + ch * 16 + c)) * HW + row * WW + gcol];
            xs[c][i][col] = v;
        }
        __syncthreads();

        u64 a0 = 0ull, a1 = 0ull;
#pragma unroll
        for (int i = 0; i < 7; ++i) {
            const float* xrow = &xs[cl][i][p0];
            u64 xv0 = lds64(xrow);
            u64 xv1 = lds64(xrow + 2);
#pragma unroll
            for (int j = 0; j < 7; ++j) {
                u64 av0 = lds64(&at[i * 7 + j][p0]);
                u64 av1 = lds64(&at[i * 7 + j][p0 + 2]);
                fma2(a0, av0, xv0);
                fma2(a1, av1, xv1);
                xv0 = xv1;
                xv1 = lds64(xrow + 2 * j + 4);
            }
        }
        int c = chalf + ch * 16 + cl;
        size_t o = (size_t)(b * CC + c) * HW + h * WW + p0;
        float2 r0 = unpack2(a0), r1 = unpack2(a1);
        *reinterpret_cast<float2*>(&out[o]) = r0;
        *reinterpret_cast<float2*>(&out[o + 2]) = r1;
    }
}

// =====================================================================
extern "C" void kernel_launch(void* const* d_in, const int* in_sizes, int n_in,
                              void* d_out, int out_size)
{
    const float* x  = (const float*)d_in[0];
    const float* W1 = (const float*)d_in[1];
    const float* b1 = (const float*)d_in[2];
    const float* W2 = (const float*)d_in[3];
    const float* b2 = (const float*)d_in[4];
    for (int i = 0; i < n_in; ++i) {
        switch (in_sizes[i]) {
            case BB * CC * HW: x  = (const float*)d_in[i]; break;
            case CO * CC * NT: W1 = (const float*)d_in[i]; break;
            case CO:           b1 = (const float*)d_in[i]; break;
            case NT * CO:      W2 = (const float*)d_in[i]; break;
            case NT:           b2 = (const float*)d_in[i]; break;
            default: break;
        }
    }
    float* out = (float*)d_out;

    prep_w1<<<6272, 256>>>(W1);
    conv1_kernel<<<dim3(28, 4, 8), 224>>>(x);
    conv2_softmax_kernel<<<dim3(56, 4), 256>>>(W2, b1, b2);
    gather_kernel<<<dim3(56, 4, 2), 224>>>(x, out);
}